// round 4
// baseline (speedup 1.0000x reference)
#include <cuda_runtime.h>
#include <cuda_bf16.h>

#define CG 16
#define HW 4096
#define NG 512            // b*g groups

// ---------------- scratch (static device allocations are allowed) ----------
__device__ __nv_bfloat16 g_x3[(size_t)NG * CG * HW];   // conv3x3 output (relu'd), 67MB
__device__ float g_ah[NG * CG * 64];
__device__ float g_aw[NG * CG * 64];
__device__ float g_cs[NG * CG * 6];            // k, d, max2, max3, V2, V3

// ---------------- warp reduce helpers --------------------------------------
__device__ __forceinline__ float wsum(float v){
  #pragma unroll
  for (int o = 16; o; o >>= 1) v += __shfl_xor_sync(0xffffffffu, v, o);
  return v;
}
__device__ __forceinline__ float wmax(float v){
  #pragma unroll
  for (int o = 16; o; o >>= 1) v = fmaxf(v, __shfl_xor_sync(0xffffffffu, v, o));
  return v;
}
__device__ __forceinline__ float wmin(float v){
  #pragma unroll
  for (int o = 16; o; o >>= 1) v = fminf(v, __shfl_xor_sync(0xffffffffu, v, o));
  return v;
}

// ---------------- packed f32x2 helpers (sm_100+ FFMA2 path) -----------------
__device__ __forceinline__ unsigned long long pk2(float lo, float hi){
  unsigned long long r;
  asm("mov.b64 %0, {%1, %2};" : "=l"(r) : "f"(lo), "f"(hi));
  return r;
}
__device__ __forceinline__ void fma2(unsigned long long& d,
                                     unsigned long long a,
                                     unsigned long long b){
  asm("fma.rn.f32x2 %0, %1, %2, %0;" : "+l"(d) : "l"(a), "l"(b));
}
__device__ __forceinline__ float2 upk2(unsigned long long v){
  float2 f;
  asm("mov.b64 {%0, %1}, %2;" : "=f"(f.x), "=f"(f.y) : "l"(v));
  return f;
}

// ---------------- dynamic smem layout for KA (floats) -----------------------
#define TILE_RP 68                 // row pitch (1 zero col + 64 data + 1 zero + 2 pad)
#define TILE_CP (18 * TILE_RP)     // channel pitch (18 rows incl. vertical halo)
#define SM_TILE 0                  // 16*18*68 = 19584 floats
#define SM_AH   19584              // 1024
#define SM_AW   20608              // 1024
#define SM_W3D  21632              // 4608 floats (duplicated {w,w} pairs)
#define SM_TOTF 26240              // total floats = 104960 bytes

__global__ void __launch_bounds__(512, 2) ka_kernel(
    const float* __restrict__ x,
    const float* __restrict__ w1, const float* __restrict__ b1,
    const float* __restrict__ wh, const float* __restrict__ bh,
    const float* __restrict__ ww, const float* __restrict__ bw,
    const float* __restrict__ w3, const float* __restrict__ b3,
    const float* __restrict__ gnw, const float* __restrict__ gnb)
{
  extern __shared__ float sm[];
  float* tile  = sm + SM_TILE;
  float* s_ah  = sm + SM_AH;
  float* s_aw  = sm + SM_AW;
  float* s_w3d = sm + SM_W3D;
  // phase-1 regions live inside the tile region (freed before conv)
  float* s_xh = sm;            // [16][64]
  float* s_xw = sm + 1024;     // [16][64]
  float* s_y  = sm + 2048;     // [16][128]
  float* s_W  = sm + 4096;     // W1(256) Wh(256) Ww(256)
  float* s_bb = sm + 4864;     // b1(16) bh(16) bw(16)

  __shared__ float s_b3[16];
  __shared__ float schmax3[16], schsum3[16];
  __shared__ float schsum1[16], schmax1[16], schmin1[16];
  __shared__ float s_rg[16], s_rq[16];
  __shared__ float s_mu, s_rs;

  const int t = threadIdx.x, warp = t >> 5, lane = t & 31;
  const int g = blockIdx.x;
  const float* xg = x + (size_t)g * CG * HW;

  // ---- load small weights / init reductions ----
  if (t < 256) { s_W[t] = w1[t]; s_W[256 + t] = wh[t]; s_W[512 + t] = ww[t]; }
  if (t < 16) {
    s_bb[t] = b1[t]; s_bb[16 + t] = bh[t]; s_bb[32 + t] = bw[t];
    s_b3[t] = b3[t]; schmax3[t] = 0.f; schsum3[t] = 0.f;
  }
  for (int i = t; i < 2304; i += 512) {
    float v = w3[i];
    s_w3d[2 * i] = v; s_w3d[2 * i + 1] = v;
  }

  // ---- phase 1: row/col means (warp == channel) ----
  {
    const float* xc = xg + warp * HW;
    float cs0 = 0.f, cs1 = 0.f;
    for (int i = 0; i < 64; i++) {
      float v0 = xc[i * 64 + lane];
      float v1 = xc[i * 64 + lane + 32];
      cs0 += v0; cs1 += v1;
      float rsum = wsum(v0 + v1);
      if (lane == 0) s_xh[warp * 64 + i] = rsum * (1.f / 64.f);
    }
    s_xw[warp * 64 + lane]      = cs0 * (1.f / 64.f);
    s_xw[warp * 64 + lane + 32] = cs1 * (1.f / 64.f);
  }
  __syncthreads();

  // ---- phase 1b: y = relu(W1 @ [xh;xw] + b1) ----
  if (t < 128) {
    float in[16];
    #pragma unroll
    for (int i = 0; i < 16; i++)
      in[i] = (t < 64) ? s_xh[i * 64 + t] : s_xw[i * 64 + (t - 64)];
    #pragma unroll
    for (int o = 0; o < 16; o++) {
      float acc = s_bb[o];
      #pragma unroll
      for (int i = 0; i < 16; i++) acc = fmaf(s_W[o * 16 + i], in[i], acc);
      s_y[o * 128 + t] = fmaxf(acc, 0.f);
    }
  }
  __syncthreads();
  // ---- a_h = sigmoid(Wh @ y_h + bh), a_w = sigmoid(Ww @ y_w + bw) ----
  if (t < 128) {
    const int half = t >> 6, col = t & 63;
    const float* Wm = s_W + 256 + half * 256;
    const float* bm = s_bb + 16 + half * 16;
    float in[16];
    #pragma unroll
    for (int i = 0; i < 16; i++) in[i] = s_y[i * 128 + t];
    float* dst  = half ? s_aw : s_ah;
    float* gdst = half ? (g_aw + g * 1024) : (g_ah + g * 1024);
    #pragma unroll
    for (int o = 0; o < 16; o++) {
      float acc = bm[o];
      #pragma unroll
      for (int i = 0; i < 16; i++) acc = fmaf(Wm[o * 16 + i], in[i], acc);
      float sg = 1.f / (1.f + __expf(-acc));
      dst[o * 64 + col] = sg;
      gdst[o * 64 + col] = sg;
    }
  }

  // ---- phase 2: conv3x3 (packed f32x2) + x1/x3 statistics, 4 strips --------
  float gs = 0.f, gsq = 0.f;
  float c1sum = 0.f, c1max = -1e30f, c1min = 1e30f;
  const int ocp = t >> 6, oc0 = ocp * 2, oc1 = oc0 + 1;
  float m30 = 0.f, m31 = 0.f, s30 = 0.f, s31 = 0.f;
  const unsigned long long* w3du =
      reinterpret_cast<const unsigned long long*>(s_w3d);

  for (int r0 = 0; r0 < 64; r0 += 16) {
    __syncthreads();                       // previous tile readers done
    // load strip (rows r0-1 .. r0+16) with zero halo
    for (int idx = t; idx < 4608; idx += 512) {
      int c = idx / 288;
      int rem = idx - c * 288;
      int rr = rem >> 4, q = rem & 15;
      int gr = r0 - 1 + rr;
      float4 v = make_float4(0.f, 0.f, 0.f, 0.f);
      if ((unsigned)gr < 64u)
        v = *reinterpret_cast<const float4*>(xg + c * HW + gr * 64 + q * 4);
      float* d = tile + c * TILE_CP + rr * TILE_RP + 1 + q * 4;
      d[0] = v.x; d[1] = v.y; d[2] = v.z; d[3] = v.w;
    }
    if (t < 288) {
      int c = t / 18, rr = t - c * 18;
      float* row = tile + c * TILE_CP + rr * TILE_RP;
      row[0] = 0.f; row[65] = 0.f;
    }
    __syncthreads();

    // x1 stats (warp == channel)
    {
      const float* tc  = tile + warp * TILE_CP;
      const float* ahc = s_ah + warp * 64;
      const float* awc = s_aw + warp * 64;
      float aw0 = awc[lane], aw1 = awc[lane + 32];
      #pragma unroll 4
      for (int r = 0; r < 16; r++) {
        float a = ahc[r0 + r];
        const float* rowp = tc + (r + 1) * TILE_RP + 1;
        float v0 = rowp[lane] * a * aw0;
        float v1 = rowp[lane + 32] * a * aw1;
        gs += v0 + v1;
        gsq += v0 * v0 + v1 * v1;
        c1sum += v0 + v1;
        c1max = fmaxf(c1max, fmaxf(v0, v1));
        c1min = fminf(c1min, fminf(v0, v1));
      }
    }

    // conv: each thread computes 2 tiles of (2 outch x 8 px), packed pairs
    #pragma unroll 1
    for (int it = 0; it < 2; it++) {
      int ti = (t & 63) + (it << 6);
      int rr = ti >> 3, cb = ti & 7;
      unsigned long long A0[4], A1[4];
      #pragma unroll
      for (int p = 0; p < 4; p++) { A0[p] = 0ull; A1[p] = 0ull; }
      const float* tb = tile + rr * TILE_RP + cb * 8;
      #pragma unroll 1
      for (int ci = 0; ci < 16; ci++) {
        const float* tcb = tb + ci * TILE_CP;
        const unsigned long long* wa = w3du + oc0 * 144 + ci * 9;
        const unsigned long long* wb = w3du + oc1 * 144 + ci * 9;
        #pragma unroll
        for (int dr = 0; dr < 3; dr++) {
          const float4 q0 = *reinterpret_cast<const float4*>(tcb + dr * TILE_RP);
          const float4 q1 = *reinterpret_cast<const float4*>(tcb + dr * TILE_RP + 4);
          const float2 q2 = *reinterpret_cast<const float2*>(tcb + dr * TILE_RP + 8);
          unsigned long long E0 = pk2(q0.x, q0.y), E1 = pk2(q0.z, q0.w);
          unsigned long long E2 = pk2(q1.x, q1.y), E3 = pk2(q1.z, q1.w);
          unsigned long long E4 = pk2(q2.x, q2.y);
          unsigned long long O0 = pk2(q0.y, q0.z), O1 = pk2(q0.w, q1.x);
          unsigned long long O2 = pk2(q1.y, q1.z), O3 = pk2(q1.w, q2.x);
          {
            unsigned long long u0 = wa[dr * 3], u1 = wa[dr * 3 + 1], u2 = wa[dr * 3 + 2];
            fma2(A0[0], u0, E0); fma2(A0[0], u1, O0); fma2(A0[0], u2, E1);
            fma2(A0[1], u0, E1); fma2(A0[1], u1, O1); fma2(A0[1], u2, E2);
            fma2(A0[2], u0, E2); fma2(A0[2], u1, O2); fma2(A0[2], u2, E3);
            fma2(A0[3], u0, E3); fma2(A0[3], u1, O3); fma2(A0[3], u2, E4);
          }
          {
            unsigned long long u0 = wb[dr * 3], u1 = wb[dr * 3 + 1], u2 = wb[dr * 3 + 2];
            fma2(A1[0], u0, E0); fma2(A1[0], u1, O0); fma2(A1[0], u2, E1);
            fma2(A1[1], u0, E1); fma2(A1[1], u1, O1); fma2(A1[1], u2, E2);
            fma2(A1[2], u0, E2); fma2(A1[2], u1, O2); fma2(A1[2], u2, E3);
            fma2(A1[3], u0, E3); fma2(A1[3], u1, O3); fma2(A1[3], u2, E4);
          }
        }
      }
      int grow = r0 + rr;
      float bz0 = s_b3[oc0], bz1 = s_b3[oc1];
      __nv_bfloat162 h0[4], h1[4];
      #pragma unroll
      for (int p = 0; p < 4; p++) {
        float2 f0 = upk2(A0[p]);
        float2 f1 = upk2(A1[p]);
        float a0 = fmaxf(f0.x + bz0, 0.f), a1 = fmaxf(f0.y + bz0, 0.f);
        float b0v = fmaxf(f1.x + bz1, 0.f), b1v = fmaxf(f1.y + bz1, 0.f);
        m30 = fmaxf(m30, fmaxf(a0, a1)); s30 += a0 + a1;
        m31 = fmaxf(m31, fmaxf(b0v, b1v)); s31 += b0v + b1v;
        h0[p] = __floats2bfloat162_rn(a0, a1);
        h1[p] = __floats2bfloat162_rn(b0v, b1v);
      }
      __nv_bfloat16* o0 = g_x3 + ((size_t)g * CG + oc0) * HW + grow * 64 + cb * 8;
      __nv_bfloat16* o1 = g_x3 + ((size_t)g * CG + oc1) * HW + grow * 64 + cb * 8;
      *reinterpret_cast<uint4*>(o0) = *reinterpret_cast<uint4*>(h0);
      *reinterpret_cast<uint4*>(o1) = *reinterpret_cast<uint4*>(h1);
    }
  }

  // ---- reductions ----
  gs = wsum(gs); gsq = wsum(gsq);
  c1sum = wsum(c1sum); c1max = wmax(c1max); c1min = wmin(c1min);
  if (lane == 0) {
    s_rg[warp] = gs; s_rq[warp] = gsq;
    schsum1[warp] = c1sum; schmax1[warp] = c1max; schmin1[warp] = c1min;
  }
  atomicAdd(&schsum3[oc0], s30);
  atomicAdd(&schsum3[oc1], s31);
  atomicMax(reinterpret_cast<int*>(&schmax3[oc0]), __float_as_int(m30)); // relu >= 0
  atomicMax(reinterpret_cast<int*>(&schmax3[oc1]), __float_as_int(m31));
  __syncthreads();
  if (t == 0) {
    float a = 0.f, bq = 0.f;
    #pragma unroll
    for (int i = 0; i < 16; i++) { a += s_rg[i]; bq += s_rq[i]; }
    float mu = a * (1.f / 65536.f);
    float var = bq * (1.f / 65536.f) - mu * mu;
    s_mu = mu; s_rs = rsqrtf(var + 1e-5f);
  }
  __syncthreads();
  if (t < 16) {
    int c = t;
    float k = s_rs * gnw[c];
    float d = gnb[c] - s_mu * k;
    float mx1 = (k >= 0.f) ? schmax1[c] : schmin1[c];
    float max2 = mx1 * k + d;
    float V2 = schsum1[c] * (1.f / 4096.f) * k + d;
    float V3 = schsum3[c] * (1.f / 4096.f);
    float* cs = g_cs + (g * CG + c) * 6;
    cs[0] = k; cs[1] = d; cs[2] = max2; cs[3] = schmax3[c]; cs[4] = V2; cs[5] = V3;
  }
}

// ---------------------------------------------------------------------------
// KB: 256 threads, 3 CTAs/SM to hide softmax barrier bubbles.
__global__ void __launch_bounds__(256, 3) kb_kernel(const float* __restrict__ x,
                                                    float* __restrict__ out)
{
  __shared__ float s_s[4096];
  __shared__ float s_ah[1024], s_aw[1024];
  __shared__ float s_k[16], s_e2[16], s_m3[16], s_w2[16], s_w3[16];
  __shared__ float s_r1[8];
  __shared__ float s_smax, s_sinv;

  const int t = threadIdx.x, warp = t >> 5, lane = t & 31;
  const int g = blockIdx.x;
  const float* xg = x + (size_t)g * CG * HW;
  const __nv_bfloat16* x3g = g_x3 + (size_t)g * CG * HW;

  for (int i = t; i < 1024; i += 256) {
    s_ah[i] = g_ah[g * 1024 + i];
    s_aw[i] = g_aw[g * 1024 + i];
  }
  if (t < 16) {
    const float* cs = g_cs + (g * CG + t) * 6;
    s_k[t]  = cs[0];
    s_e2[t] = cs[1] - cs[2];   // d - max2
    s_m3[t] = cs[3];
    s_w3[t] = cs[4];           // V2 (divided by Z3 below)
    s_w2[t] = cs[5];           // V3 (divided by Z2 below)
  }
  __syncthreads();

  // pass 1: per-channel Z2, Z3 (each warp handles 2 channels, float2/bf162)
  #pragma unroll 1
  for (int cc = 0; cc < 2; cc++) {
    const int c = warp + cc * 8;
    float k = s_k[c], e2 = s_e2[c], m3 = s_m3[c];
    const float* xc = xg + c * HW;
    const __nv_bfloat16* x3c = x3g + c * HW;
    const float* ahc = s_ah + c * 64;
    float aw0 = s_aw[c * 64 + lane * 2];
    float aw1 = s_aw[c * 64 + lane * 2 + 1];
    float z2 = 0.f, z3 = 0.f;
    #pragma unroll 4
    for (int m = 0; m < 64; m++) {
      int l2 = m * 64 + lane * 2;
      float2 xv = *reinterpret_cast<const float2*>(xc + l2);
      __nv_bfloat162 x3v = *reinterpret_cast<const __nv_bfloat162*>(x3c + l2);
      float a = ahc[m];
      z2 += __expf(fmaf(xv.x * a * aw0, k, e2)) + __expf(fmaf(xv.y * a * aw1, k, e2));
      z3 += __expf(__bfloat162float(x3v.x) - m3) + __expf(__bfloat162float(x3v.y) - m3);
    }
    z2 = wsum(z2); z3 = wsum(z3);
    if (lane == 0) { s_w3[c] = s_w3[c] / z3; s_w2[c] = s_w2[c] / z2; }
  }
  __syncthreads();

  // pass 2: s logits (2-channel-chunk over 8 reps of paired pixels)
  #pragma unroll 1
  for (int rep = 0; rep < 8; rep++) {
    int l0 = (t + rep * 256) * 2;
    int i = l0 >> 6, j = l0 & 63;
    float ax = 0.f, ay = 0.f;
    #pragma unroll
    for (int c = 0; c < 8; c++) {
      float2 xv = *reinterpret_cast<const float2*>(xg + c * HW + l0);
      __nv_bfloat162 x3v = *reinterpret_cast<const __nv_bfloat162*>(x3g + c * HW + l0);
      float ah = s_ah[c * 64 + i];
      float x1x = xv.x * ah * s_aw[c * 64 + j];
      float x1y = xv.y * ah * s_aw[c * 64 + j + 1];
      ax += s_w2[c] * __expf(fmaf(x1x, s_k[c], s_e2[c]));
      ay += s_w2[c] * __expf(fmaf(x1y, s_k[c], s_e2[c]));
      ax += s_w3[c] * __expf(__bfloat162float(x3v.x) - s_m3[c]);
      ay += s_w3[c] * __expf(__bfloat162float(x3v.y) - s_m3[c]);
    }
    s_s[l0] = ax; s_s[l0 + 1] = ay;
  }
  float lmax = -1e30f;
  #pragma unroll 1
  for (int rep = 0; rep < 8; rep++) {
    int l0 = (t + rep * 256) * 2;
    int i = l0 >> 6, j = l0 & 63;
    float ax = s_s[l0], ay = s_s[l0 + 1];
    #pragma unroll
    for (int c = 8; c < 16; c++) {
      float2 xv = *reinterpret_cast<const float2*>(xg + c * HW + l0);
      __nv_bfloat162 x3v = *reinterpret_cast<const __nv_bfloat162*>(x3g + c * HW + l0);
      float ah = s_ah[c * 64 + i];
      float x1x = xv.x * ah * s_aw[c * 64 + j];
      float x1y = xv.y * ah * s_aw[c * 64 + j + 1];
      ax += s_w2[c] * __expf(fmaf(x1x, s_k[c], s_e2[c]));
      ay += s_w2[c] * __expf(fmaf(x1y, s_k[c], s_e2[c]));
      ax += s_w3[c] * __expf(__bfloat162float(x3v.x) - s_m3[c]);
      ay += s_w3[c] * __expf(__bfloat162float(x3v.y) - s_m3[c]);
    }
    s_s[l0] = ax; s_s[l0 + 1] = ay;
    lmax = fmaxf(lmax, fmaxf(ax, ay));
  }
  lmax = wmax(lmax);
  if (lane == 0) s_r1[warp] = lmax;
  __syncthreads();
  if (t == 0) {
    float m = -1e30f;
    #pragma unroll
    for (int i = 0; i < 8; i++) m = fmaxf(m, s_r1[i]);
    s_smax = m;
  }
  __syncthreads();
  float lsum = 0.f;
  {
    float smax = s_smax;
    #pragma unroll 1
    for (int rep = 0; rep < 8; rep++) {
      int l0 = (t + rep * 256) * 2;
      float ex = __expf(s_s[l0] - smax);
      float ey = __expf(s_s[l0 + 1] - smax);
      s_s[l0] = ex; s_s[l0 + 1] = ey;      // store exp once; normalize later
      lsum += ex + ey;
    }
  }
  lsum = wsum(lsum);
  if (lane == 0) s_r1[warp] = lsum;
  __syncthreads();
  if (t == 0) {
    float a = 0.f;
    #pragma unroll
    for (int i = 0; i < 8; i++) a += s_r1[i];
    s_sinv = 1.f / a;
  }
  __syncthreads();

  // pass 3: out = x * (e * sinv)
  float* og = out + (size_t)g * CG * HW;
  float sinv = s_sinv;
  #pragma unroll 1
  for (int c = 0; c < 16; c++) {
    #pragma unroll
    for (int rep = 0; rep < 8; rep++) {
      int l0 = (t + rep * 256) * 2;
      float2 xv = *reinterpret_cast<const float2*>(xg + c * HW + l0);
      float2 ov;
      ov.x = xv.x * (s_s[l0] * sinv);
      ov.y = xv.y * (s_s[l0 + 1] * sinv);
      *reinterpret_cast<float2*>(og + c * HW + l0) = ov;
    }
  }
}

// ---------------------------------------------------------------------------
extern "C" void kernel_launch(void* const* d_in, const int* in_sizes, int n_in,
                              void* d_out, int out_size)
{
  const float* x   = (const float*)d_in[0];
  const float* w1  = (const float*)d_in[1];
  const float* b1  = (const float*)d_in[2];
  const float* wh  = (const float*)d_in[3];
  const float* bh  = (const float*)d_in[4];
  const float* ww  = (const float*)d_in[5];
  const float* bw  = (const float*)d_in[6];
  const float* w3  = (const float*)d_in[7];
  const float* b3  = (const float*)d_in[8];
  const float* gnw = (const float*)d_in[9];
  const float* gnb = (const float*)d_in[10];

  cudaFuncSetAttribute(ka_kernel, cudaFuncAttributeMaxDynamicSharedMemorySize,
                       SM_TOTF * (int)sizeof(float));
  ka_kernel<<<NG, 512, SM_TOTF * sizeof(float)>>>(x, w1, b1, wh, bh, ww, bw, w3, b3, gnw, gnb);
  kb_kernel<<<NG, 256>>>(x, (float*)d_out);
}

// round 5
// speedup vs baseline: 1.1473x; 1.1473x over previous
#include <cuda_runtime.h>
#include <cuda_bf16.h>

#define CG 16
#define HW 4096
#define NG 512            // b*g groups

// ---------------- scratch (static device allocations are allowed) ----------
__device__ __nv_bfloat16 g_x3[(size_t)NG * CG * HW];   // conv3x3 output (relu'd), 67MB
__device__ float g_ah[NG * CG * 64];
__device__ float g_aw[NG * CG * 64];
__device__ float g_cs[NG * CG * 2];            // max3, V3

// ---------------- warp reduce helpers --------------------------------------
__device__ __forceinline__ float wsum(float v){
  #pragma unroll
  for (int o = 16; o; o >>= 1) v += __shfl_xor_sync(0xffffffffu, v, o);
  return v;
}
__device__ __forceinline__ float wmax(float v){
  #pragma unroll
  for (int o = 16; o; o >>= 1) v = fmaxf(v, __shfl_xor_sync(0xffffffffu, v, o));
  return v;
}
__device__ __forceinline__ float wmin(float v){
  #pragma unroll
  for (int o = 16; o; o >>= 1) v = fminf(v, __shfl_xor_sync(0xffffffffu, v, o));
  return v;
}

// ---------------- packed f32x2 helpers (sm_100+ FFMA2 path) -----------------
__device__ __forceinline__ unsigned long long pk2(float lo, float hi){
  unsigned long long r;
  asm("mov.b64 %0, {%1, %2};" : "=l"(r) : "f"(lo), "f"(hi));
  return r;
}
__device__ __forceinline__ void fma2(unsigned long long& d,
                                     unsigned long long a,
                                     unsigned long long b){
  asm("fma.rn.f32x2 %0, %1, %2, %0;" : "+l"(d) : "l"(a), "l"(b));
}
__device__ __forceinline__ float2 upk2(unsigned long long v){
  float2 f;
  asm("mov.b64 {%0, %1}, %2;" : "=f"(f.x), "=f"(f.y) : "l"(v));
  return f;
}

// ---------------- dynamic smem layout for KA (floats) -----------------------
#define TILE_RP 68                 // row pitch (1 zero col + 64 data + 1 zero + 2 pad)
#define TILE_CP (18 * TILE_RP)     // channel pitch (18 rows incl. vertical halo)
#define SM_TILE 0                  // 16*18*68 = 19584 floats
#define SM_W3D  19584              // 4608 floats (duplicated {w,w} weight pairs)
#define SM_RS   24192              // 1024 floats: per-channel row sums (x_h numerators)
#define SM_TOTF 25216              // 100864 bytes

__global__ void __launch_bounds__(512, 2) ka_kernel(
    const float* __restrict__ x,
    const float* __restrict__ w1, const float* __restrict__ b1,
    const float* __restrict__ wh, const float* __restrict__ bh,
    const float* __restrict__ ww, const float* __restrict__ bw,
    const float* __restrict__ w3, const float* __restrict__ b3)
{
  extern __shared__ float sm[];
  float* tile  = sm + SM_TILE;
  float* s_w3d = sm + SM_W3D;
  float* s_rs  = sm + SM_RS;       // [16][64] row sums
  // end-phase overlay (inside tile region, used after last strip sync)
  float* s_xw = sm + 1024;         // [16][64] col sums
  float* s_y  = sm + 2048;         // [16][128]
  float* s_W  = sm + 4096;         // W1(256) Wh(256) Ww(256)
  float* s_bb = sm + 4864;         // b1(16) bh(16) bw(16)

  __shared__ float s_b3[16];
  __shared__ float schmax3[16], schsum3[16];

  const int t = threadIdx.x, warp = t >> 5, lane = t & 31;
  const int g = blockIdx.x;
  const float* xg = x + (size_t)g * CG * HW;

  if (t < 16) { s_b3[t] = b3[t]; schmax3[t] = 0.f; schsum3[t] = 0.f; }
  for (int i = t; i < 2304; i += 512) {
    float v = w3[i];
    s_w3d[2 * i] = v; s_w3d[2 * i + 1] = v;
  }

  // ---- strip loop: load, row/col sums, conv3x3 ------------------------------
  float csum0 = 0.f, csum1 = 0.f;       // per-warp(=channel) column sums
  const int ocp = t >> 6, oc0 = ocp * 2, oc1 = oc0 + 1;
  float m30 = 0.f, m31 = 0.f, s30 = 0.f, s31 = 0.f;
  const unsigned long long* w3du =
      reinterpret_cast<const unsigned long long*>(s_w3d);

  for (int r0 = 0; r0 < 64; r0 += 16) {
    __syncthreads();                       // previous tile readers done
    // load strip (rows r0-1 .. r0+16) with zero halo
    for (int idx = t; idx < 4608; idx += 512) {
      int c = idx / 288;
      int rem = idx - c * 288;
      int rr = rem >> 4, q = rem & 15;
      int gr = r0 - 1 + rr;
      float4 v = make_float4(0.f, 0.f, 0.f, 0.f);
      if ((unsigned)gr < 64u)
        v = *reinterpret_cast<const float4*>(xg + c * HW + gr * 64 + q * 4);
      float* d = tile + c * TILE_CP + rr * TILE_RP + 1 + q * 4;
      d[0] = v.x; d[1] = v.y; d[2] = v.z; d[3] = v.w;
    }
    if (t < 288) {
      int c = t / 18, rr = t - c * 18;
      float* row = tile + c * TILE_CP + rr * TILE_RP;
      row[0] = 0.f; row[65] = 0.f;
    }
    __syncthreads();

    // row/col sums from smem (warp == channel)
    {
      const float* tc = tile + warp * TILE_CP;
      #pragma unroll 4
      for (int r = 0; r < 16; r++) {
        const float* rowp = tc + (r + 1) * TILE_RP + 1;
        float v0 = rowp[lane];
        float v1 = rowp[lane + 32];
        csum0 += v0; csum1 += v1;
        float rsum = wsum(v0 + v1);
        if (lane == 0) s_rs[warp * 64 + r0 + r] = rsum;
      }
    }

    // conv: each thread computes 2 tiles of (2 outch x 8 px), packed f32x2
    #pragma unroll 1
    for (int it = 0; it < 2; it++) {
      int ti = (t & 63) + (it << 6);
      int rr = ti >> 3, cb = ti & 7;
      unsigned long long A0[4], A1[4];
      #pragma unroll
      for (int p = 0; p < 4; p++) { A0[p] = 0ull; A1[p] = 0ull; }
      const float* tb = tile + rr * TILE_RP + cb * 8;
      #pragma unroll 1
      for (int ci = 0; ci < 16; ci++) {
        const float* tcb = tb + ci * TILE_CP;
        const unsigned long long* wa = w3du + oc0 * 144 + ci * 9;
        const unsigned long long* wb = w3du + oc1 * 144 + ci * 9;
        #pragma unroll
        for (int dr = 0; dr < 3; dr++) {
          const float4 q0 = *reinterpret_cast<const float4*>(tcb + dr * TILE_RP);
          const float4 q1 = *reinterpret_cast<const float4*>(tcb + dr * TILE_RP + 4);
          const float2 q2 = *reinterpret_cast<const float2*>(tcb + dr * TILE_RP + 8);
          unsigned long long E0 = pk2(q0.x, q0.y), E1 = pk2(q0.z, q0.w);
          unsigned long long E2 = pk2(q1.x, q1.y), E3 = pk2(q1.z, q1.w);
          unsigned long long E4 = pk2(q2.x, q2.y);
          unsigned long long O0 = pk2(q0.y, q0.z), O1 = pk2(q0.w, q1.x);
          unsigned long long O2 = pk2(q1.y, q1.z), O3 = pk2(q1.w, q2.x);
          {
            unsigned long long u0 = wa[dr * 3], u1 = wa[dr * 3 + 1], u2 = wa[dr * 3 + 2];
            fma2(A0[0], u0, E0); fma2(A0[0], u1, O0); fma2(A0[0], u2, E1);
            fma2(A0[1], u0, E1); fma2(A0[1], u1, O1); fma2(A0[1], u2, E2);
            fma2(A0[2], u0, E2); fma2(A0[2], u1, O2); fma2(A0[2], u2, E3);
            fma2(A0[3], u0, E3); fma2(A0[3], u1, O3); fma2(A0[3], u2, E4);
          }
          {
            unsigned long long u0 = wb[dr * 3], u1 = wb[dr * 3 + 1], u2 = wb[dr * 3 + 2];
            fma2(A1[0], u0, E0); fma2(A1[0], u1, O0); fma2(A1[0], u2, E1);
            fma2(A1[1], u0, E1); fma2(A1[1], u1, O1); fma2(A1[1], u2, E2);
            fma2(A1[2], u0, E2); fma2(A1[2], u1, O2); fma2(A1[2], u2, E3);
            fma2(A1[3], u0, E3); fma2(A1[3], u1, O3); fma2(A1[3], u2, E4);
          }
        }
      }
      int grow = r0 + rr;
      float bz0 = s_b3[oc0], bz1 = s_b3[oc1];
      __nv_bfloat162 h0[4], h1[4];
      #pragma unroll
      for (int p = 0; p < 4; p++) {
        float2 f0 = upk2(A0[p]);
        float2 f1 = upk2(A1[p]);
        float a0 = fmaxf(f0.x + bz0, 0.f), a1 = fmaxf(f0.y + bz0, 0.f);
        float b0v = fmaxf(f1.x + bz1, 0.f), b1v = fmaxf(f1.y + bz1, 0.f);
        m30 = fmaxf(m30, fmaxf(a0, a1)); s30 += a0 + a1;
        m31 = fmaxf(m31, fmaxf(b0v, b1v)); s31 += b0v + b1v;
        h0[p] = __floats2bfloat162_rn(a0, a1);
        h1[p] = __floats2bfloat162_rn(b0v, b1v);
      }
      __nv_bfloat16* o0 = g_x3 + ((size_t)g * CG + oc0) * HW + grow * 64 + cb * 8;
      __nv_bfloat16* o1 = g_x3 + ((size_t)g * CG + oc1) * HW + grow * 64 + cb * 8;
      *reinterpret_cast<uint4*>(o0) = *reinterpret_cast<uint4*>(h0);
      *reinterpret_cast<uint4*>(o1) = *reinterpret_cast<uint4*>(h1);
    }
  }
  __syncthreads();                         // all tile reads done; overlay is safe

  // ---- end phase: finalize col sums, x3 stats, 1x1 convs -------------------
  s_xw[warp * 64 + lane]      = csum0;
  s_xw[warp * 64 + lane + 32] = csum1;
  if (t < 256) { s_W[t] = w1[t]; s_W[256 + t] = wh[t]; s_W[512 + t] = ww[t]; }
  if (t < 16) { s_bb[t] = b1[t]; s_bb[16 + t] = bh[t]; s_bb[32 + t] = bw[t]; }
  atomicAdd(&schsum3[oc0], s30);
  atomicAdd(&schsum3[oc1], s31);
  atomicMax(reinterpret_cast<int*>(&schmax3[oc0]), __float_as_int(m30)); // relu >= 0
  atomicMax(reinterpret_cast<int*>(&schmax3[oc1]), __float_as_int(m31));
  __syncthreads();

  if (t < 16) {
    float* cs = g_cs + (g * CG + t) * 2;
    cs[0] = schmax3[t];
    cs[1] = schsum3[t] * (1.f / 4096.f);
  }

  // y = relu(W1 @ [xh;xw] + b1)
  if (t < 128) {
    float in[16];
    #pragma unroll
    for (int i = 0; i < 16; i++) {
      float raw = (t < 64) ? s_rs[i * 64 + t] : s_xw[i * 64 + (t - 64)];
      in[i] = raw * (1.f / 64.f);
    }
    #pragma unroll
    for (int o = 0; o < 16; o++) {
      float acc = s_bb[o];
      #pragma unroll
      for (int i = 0; i < 16; i++) acc = fmaf(s_W[o * 16 + i], in[i], acc);
      s_y[o * 128 + t] = fmaxf(acc, 0.f);
    }
  }
  __syncthreads();
  // a_h = sigmoid(Wh @ y_h + bh), a_w = sigmoid(Ww @ y_w + bw) -> gmem
  if (t < 128) {
    const int half = t >> 6, col = t & 63;
    const float* Wm = s_W + 256 + half * 256;
    const float* bm = s_bb + 16 + half * 16;
    float in[16];
    #pragma unroll
    for (int i = 0; i < 16; i++) in[i] = s_y[i * 128 + t];
    float* gdst = half ? (g_aw + g * 1024) : (g_ah + g * 1024);
    #pragma unroll
    for (int o = 0; o < 16; o++) {
      float acc = bm[o];
      #pragma unroll
      for (int i = 0; i < 16; i++) acc = fmaf(Wm[o * 16 + i], in[i], acc);
      gdst[o * 64 + col] = 1.f / (1.f + __expf(-acc));
    }
  }
}

// ---------------------------------------------------------------------------
// KB: 512 threads (1 CTA/SM keeps the per-group 384KB working set L2-resident
// across its passes). pass0 = x1 statistics, pass1 = Z2/Z3, pass2 = logits,
// then softmax (exp stored once) and the final scale.
__global__ void __launch_bounds__(512) kb_kernel(const float* __restrict__ x,
                                                 const float* __restrict__ gnw,
                                                 const float* __restrict__ gnb,
                                                 float* __restrict__ out)
{
  __shared__ float s_s[4096];
  __shared__ float s_ah[1024], s_aw[1024];
  __shared__ float s_k[16], s_e2[16], s_m3[16], s_w2[16], s_w3[16];
  __shared__ float schsum1[16], schsq1[16], schmax1[16], schmin1[16];
  __shared__ float s_r1[16];
  __shared__ float s_mu, s_rsd, s_smax, s_sinv;

  const int t = threadIdx.x, warp = t >> 5, lane = t & 31;
  const int g = blockIdx.x;
  const float* xg = x + (size_t)g * CG * HW;
  const __nv_bfloat16* x3g = g_x3 + (size_t)g * CG * HW;

  for (int i = t; i < 1024; i += 512) {
    s_ah[i] = g_ah[g * 1024 + i];
    s_aw[i] = g_aw[g * 1024 + i];
  }
  __syncthreads();

  // ---- pass 0: x1 statistics (warp == channel) ----
  {
    const int c = warp;
    const float* xc = xg + c * HW;
    const float* ahc = s_ah + c * 64;
    float aw0 = s_aw[c * 64 + lane * 2];
    float aw1 = s_aw[c * 64 + lane * 2 + 1];
    float sum = 0.f, sq = 0.f, mx = -1e30f, mn = 1e30f;
    #pragma unroll 4
    for (int m = 0; m < 64; m++) {
      float2 xv = *reinterpret_cast<const float2*>(xc + m * 64 + lane * 2);
      float a = ahc[m];
      float v0 = xv.x * a * aw0;
      float v1 = xv.y * a * aw1;
      sum += v0 + v1;
      sq += v0 * v0 + v1 * v1;
      mx = fmaxf(mx, fmaxf(v0, v1));
      mn = fminf(mn, fminf(v0, v1));
    }
    sum = wsum(sum); sq = wsum(sq); mx = wmax(mx); mn = wmin(mn);
    if (lane == 0) {
      schsum1[c] = sum; schsq1[c] = sq; schmax1[c] = mx; schmin1[c] = mn;
    }
  }
  __syncthreads();
  if (t == 0) {
    float a = 0.f, bq = 0.f;
    #pragma unroll
    for (int i = 0; i < 16; i++) { a += schsum1[i]; bq += schsq1[i]; }
    float mu = a * (1.f / 65536.f);
    float var = bq * (1.f / 65536.f) - mu * mu;
    s_mu = mu; s_rsd = rsqrtf(var + 1e-5f);
  }
  __syncthreads();
  if (t < 16) {
    int c = t;
    float k = s_rsd * gnw[c];
    float d = gnb[c] - s_mu * k;
    float mx1 = (k >= 0.f) ? schmax1[c] : schmin1[c];
    float max2 = mx1 * k + d;
    const float* cs = g_cs + (g * CG + c) * 2;
    s_k[c]  = k;
    s_e2[c] = d - max2;
    s_m3[c] = cs[0];                          // max3
    s_w2[c] = cs[1];                          // V3 (÷ Z2 in pass 1)
    s_w3[c] = schsum1[c] * (1.f / 4096.f) * k + d;  // V2 (÷ Z3 in pass 1)
  }
  __syncthreads();

  // ---- pass 1: per-channel Z2, Z3 (warp == channel, L2-hot reads) ----
  {
    const int c = warp;
    float k = s_k[c], e2 = s_e2[c], m3 = s_m3[c];
    const float* xc = xg + c * HW;
    const __nv_bfloat16* x3c = x3g + c * HW;
    const float* ahc = s_ah + c * 64;
    float aw0 = s_aw[c * 64 + lane * 2];
    float aw1 = s_aw[c * 64 + lane * 2 + 1];
    float z2 = 0.f, z3 = 0.f;
    #pragma unroll 4
    for (int m = 0; m < 64; m++) {
      float2 xv = *reinterpret_cast<const float2*>(xc + m * 64 + lane * 2);
      __nv_bfloat162 x3v = *reinterpret_cast<const __nv_bfloat162*>(x3c + m * 64 + lane * 2);
      float a = ahc[m];
      z2 += __expf(fmaf(xv.x * a * aw0, k, e2)) + __expf(fmaf(xv.y * a * aw1, k, e2));
      z3 += __expf(__bfloat162float(x3v.x) - m3) + __expf(__bfloat162float(x3v.y) - m3);
    }
    z2 = wsum(z2); z3 = wsum(z3);
    if (lane == 0) { s_w3[c] = s_w3[c] / z3; s_w2[c] = s_w2[c] / z2; }
  }
  __syncthreads();

  // ---- pass 2: s logits ----
  float lmax = -1e30f;
  #pragma unroll 1
  for (int rep = 0; rep < 8; rep++) {
    int l = t + rep * 512;
    int i = l >> 6, j = l & 63;
    float acc = 0.f;
    #pragma unroll
    for (int c = 0; c < 16; c++) {
      float x1 = xg[c * HW + l] * s_ah[c * 64 + i] * s_aw[c * 64 + j];
      acc += s_w2[c] * __expf(fmaf(x1, s_k[c], s_e2[c]));
      acc += s_w3[c] * __expf(__bfloat162float(x3g[c * HW + l]) - s_m3[c]);
    }
    s_s[l] = acc;
    lmax = fmaxf(lmax, acc);
  }
  lmax = wmax(lmax);
  if (lane == 0) s_r1[warp] = lmax;
  __syncthreads();
  if (t == 0) {
    float m = -1e30f;
    #pragma unroll
    for (int i = 0; i < 16; i++) m = fmaxf(m, s_r1[i]);
    s_smax = m;
  }
  __syncthreads();
  float lsum = 0.f;
  {
    float smax = s_smax;
    #pragma unroll 1
    for (int rep = 0; rep < 8; rep++) {
      int l = t + rep * 512;
      float e = __expf(s_s[l] - smax);
      s_s[l] = e;                           // store exp once
      lsum += e;
    }
  }
  lsum = wsum(lsum);
  if (lane == 0) s_r1[warp] = lsum;
  __syncthreads();
  if (t == 0) {
    float a = 0.f;
    #pragma unroll
    for (int i = 0; i < 16; i++) a += s_r1[i];
    s_sinv = 1.f / a;
  }
  __syncthreads();

  // ---- pass 3: out = x * (e * sinv) ----
  float* og = out + (size_t)g * CG * HW;
  float sinv = s_sinv;
  #pragma unroll 1
  for (int c = 0; c < 16; c++) {
    #pragma unroll
    for (int rep = 0; rep < 4; rep++) {
      int l0 = (t + rep * 512) * 2;
      float2 xv = *reinterpret_cast<const float2*>(xg + c * HW + l0);
      float2 ov;
      ov.x = xv.x * (s_s[l0] * sinv);
      ov.y = xv.y * (s_s[l0 + 1] * sinv);
      *reinterpret_cast<float2*>(og + c * HW + l0) = ov;
    }
  }
}

// ---------------------------------------------------------------------------
extern "C" void kernel_launch(void* const* d_in, const int* in_sizes, int n_in,
                              void* d_out, int out_size)
{
  const float* x   = (const float*)d_in[0];
  const float* w1  = (const float*)d_in[1];
  const float* b1  = (const float*)d_in[2];
  const float* wh  = (const float*)d_in[3];
  const float* bh  = (const float*)d_in[4];
  const float* ww  = (const float*)d_in[5];
  const float* bw  = (const float*)d_in[6];
  const float* w3  = (const float*)d_in[7];
  const float* b3  = (const float*)d_in[8];
  const float* gnw = (const float*)d_in[9];
  const float* gnb = (const float*)d_in[10];

  cudaFuncSetAttribute(ka_kernel, cudaFuncAttributeMaxDynamicSharedMemorySize,
                       SM_TOTF * (int)sizeof(float));
  ka_kernel<<<NG, 512, SM_TOTF * sizeof(float)>>>(x, w1, b1, wh, bh, ww, bw, w3, b3);
  kb_kernel<<<NG, 512>>>(x, gnw, gnb, (float*)d_out);
}